// round 1
// baseline (speedup 1.0000x reference)
#include <cuda_runtime.h>

// ---------------------------------------------------------------------------
// Problem shapes
//   m1..m4 : (1,1,T,64) fp32, T = {4096, 6144, 8192, 4096}; last feature = sorted time
//   Q = mlp3(m1, WQ)  (relu, relu, linear), all 64x64
//   K_m = mlp3(m_m, WK[m]);  V_m = m_m (only first 32 cols matter)
//   out[i, :32] = sum_m sum_{j: t2m_j <= t1_i} (Q_i . Km_j) * Vm_j[:32]
// ---------------------------------------------------------------------------

#define T1        4096
#define TOTK      22528            // 4096+6144+8192+4096
#define CBLK      64               // key block size for state decomposition
#define NOBLK     352              // total key blocks (64+96+128+64)
#define NSTATE    356              // exclusive prefix states (nb+1 per modality)

// scratch (no allocations allowed)
__device__ float g_Q[T1 * 64];
__device__ float g_K[TOTK * 64];
__device__ float g_t2[TOTK];
__device__ float g_O[NOBLK * 2048];    // per-block sums  K^T V  (64 x 32)
__device__ float g_S[NSTATE * 2048];   // exclusive prefix states

__constant__ int c_T2[4]   = {4096, 6144, 8192, 4096};
__constant__ int c_KOFF[4] = {0, 4096, 10240, 18432};
__constant__ int c_NB[4]   = {64, 96, 128, 64};
__constant__ int c_OOFF[5] = {0, 64, 160, 288, 352};
__constant__ int c_SOFF[4] = {0, 65, 162, 291};

// ---------------------------------------------------------------------------
// Kernel 1: fused 3-layer MLP. One block = 64-row tile of one task.
// Tasks: 0 -> Q from m1 (WQ), 1..4 -> K_m from m_m (WK[m]).
// Activations live in smem (stored k-major/transposed) across all layers.
// ---------------------------------------------------------------------------
__global__ void __launch_bounds__(256) mlp_kernel(
    const float* __restrict__ m1, const float* __restrict__ m2,
    const float* __restrict__ m3, const float* __restrict__ m4,
    const float* __restrict__ WQ_w, const float* __restrict__ WQ_b,
    const float* __restrict__ WK_w, const float* __restrict__ WK_b)
{
    __shared__ float Hs[64][68];   // [k][row]  (transposed activations)
    __shared__ float Ws[64][68];   // [k][col]
    __shared__ float bs[64];

    const int task = blockIdx.y;
    const int rowsTab[5] = {4096, 4096, 6144, 8192, 4096};
    const int rows = rowsTab[task];
    const int row0 = blockIdx.x * 64;
    if (row0 >= rows) return;

    const float* X;
    if (task <= 1)      X = m1;
    else if (task == 2) X = m2;
    else if (task == 3) X = m3;
    else                X = m4;

    const float* Wb; const float* bb; float* out;
    if (task == 0) { Wb = WQ_w; bb = WQ_b; out = g_Q; }
    else {
        int m = task - 1;
        Wb = WK_w + m * 3 * 4096;
        bb = WK_b + m * 192;
        out = g_K + c_KOFF[m] * 64;
    }

    const int tid = threadIdx.x;
    // load X tile, stored transposed
    for (int idx = tid; idx < 4096; idx += 256) {
        int r = idx >> 6, c = idx & 63;
        Hs[c][r] = X[(row0 + r) * 64 + c];
    }

    const int r0 = (tid & 15) * 4;
    const int c0 = (tid >> 4) * 4;

    for (int l = 0; l < 3; l++) {
        for (int idx = tid; idx < 4096; idx += 256)
            Ws[idx >> 6][idx & 63] = Wb[l * 4096 + idx];
        if (tid < 64) bs[tid] = bb[l * 64 + tid];
        __syncthreads();

        float acc[4][4];
        #pragma unroll
        for (int rr = 0; rr < 4; rr++)
            #pragma unroll
            for (int cc = 0; cc < 4; cc++) acc[rr][cc] = bs[c0 + cc];

        #pragma unroll 8
        for (int k = 0; k < 64; k++) {
            float4 h4 = *(const float4*)&Hs[k][r0];
            float4 w4 = *(const float4*)&Ws[k][c0];
            acc[0][0] += h4.x * w4.x; acc[0][1] += h4.x * w4.y; acc[0][2] += h4.x * w4.z; acc[0][3] += h4.x * w4.w;
            acc[1][0] += h4.y * w4.x; acc[1][1] += h4.y * w4.y; acc[1][2] += h4.y * w4.z; acc[1][3] += h4.y * w4.w;
            acc[2][0] += h4.z * w4.x; acc[2][1] += h4.z * w4.y; acc[2][2] += h4.z * w4.z; acc[2][3] += h4.z * w4.w;
            acc[3][0] += h4.w * w4.x; acc[3][1] += h4.w * w4.y; acc[3][2] += h4.w * w4.z; acc[3][3] += h4.w * w4.w;
        }
        if (l < 2) {
            #pragma unroll
            for (int rr = 0; rr < 4; rr++)
                #pragma unroll
                for (int cc = 0; cc < 4; cc++) acc[rr][cc] = fmaxf(acc[rr][cc], 0.0f);
        }
        __syncthreads();   // all reads of Hs/Ws done

        if (l < 2) {
            #pragma unroll
            for (int rr = 0; rr < 4; rr++)
                #pragma unroll
                for (int cc = 0; cc < 4; cc++)
                    Hs[c0 + cc][r0 + rr] = acc[rr][cc];
        } else {
            #pragma unroll
            for (int rr = 0; rr < 4; rr++) {
                float4 o4 = make_float4(acc[rr][0], acc[rr][1], acc[rr][2], acc[rr][3]);
                *(float4*)&out[(row0 + r0 + rr) * 64 + c0] = o4;
            }
        }
    }
}

// ---------------------------------------------------------------------------
// Kernel 2: per key-block outer-product sums O_b = K_blk^T V_blk (64 x 32),
// and extraction of contiguous time arrays.
// ---------------------------------------------------------------------------
__global__ void __launch_bounds__(256) blocksum_kernel(
    const float* __restrict__ m1, const float* __restrict__ m2,
    const float* __restrict__ m3, const float* __restrict__ m4)
{
    __shared__ float Ks[64][68];
    __shared__ float Vs[64][32];

    const int blk = blockIdx.x;
    int m = 0;
    while (blk >= c_OOFF[m + 1]) m++;
    const int local = blk - c_OOFF[m];
    const float* X;
    if (m == 0) X = m1; else if (m == 1) X = m2; else if (m == 2) X = m3; else X = m4;

    const int j0g = c_KOFF[m] + local * CBLK;  // global key row
    const int j0l = local * CBLK;              // row in X
    const int tid = threadIdx.x;

    for (int idx = tid; idx < 4096; idx += 256) {
        int j = idx >> 6, d = idx & 63;
        Ks[j][d] = g_K[(j0g + j) * 64 + d];
    }
    for (int idx = tid; idx < 2048; idx += 256) {
        int j = idx >> 5, e = idx & 31;
        Vs[j][e] = X[(j0l + j) * 64 + e];
    }
    if (tid < 64) g_t2[j0g + tid] = X[(j0l + tid) * 64 + 63];
    __syncthreads();

    const int d1 = tid & 63;
    const int gg = tid >> 6;   // 0..3 -> e0 = gg*8
    float acc[8];
    #pragma unroll
    for (int q = 0; q < 8; q++) acc[q] = 0.0f;

    #pragma unroll 8
    for (int j = 0; j < CBLK; j++) {
        float kv = Ks[j][d1];
        float4 va = *(const float4*)&Vs[j][gg * 8];
        float4 vb = *(const float4*)&Vs[j][gg * 8 + 4];
        acc[0] += kv * va.x; acc[1] += kv * va.y; acc[2] += kv * va.z; acc[3] += kv * va.w;
        acc[4] += kv * vb.x; acc[5] += kv * vb.y; acc[6] += kv * vb.z; acc[7] += kv * vb.w;
    }
    float* o = &g_O[blk * 2048 + d1 * 32 + gg * 8];
    *(float4*)o       = make_float4(acc[0], acc[1], acc[2], acc[3]);
    *(float4*)(o + 4) = make_float4(acc[4], acc[5], acc[6], acc[7]);
}

// ---------------------------------------------------------------------------
// Kernel 3: exclusive prefix over block sums. One block per (modality, d1):
// 256 blocks x 32 threads. Stage all O values into smem first (fully
// pipelined loads), then do the sequential FADD chain out of smem.
// ---------------------------------------------------------------------------
__global__ void __launch_bounds__(32) prefix_kernel()
{
    __shared__ float buf[128 * 32];
    const int m  = blockIdx.x >> 6;
    const int d1 = blockIdx.x & 63;
    const int nb = c_NB[m];
    const int e  = threadIdx.x;

    for (int b = 0; b < nb; b++)
        buf[b * 32 + e] = g_O[(c_OOFF[m] + b) * 2048 + d1 * 32 + e];

    float run = 0.0f;
    for (int b = 0; b < nb; b++) {
        g_S[(c_SOFF[m] + b) * 2048 + d1 * 32 + e] = run;
        run += buf[b * 32 + e];
    }
    g_S[(c_SOFF[m] + nb) * 2048 + d1 * 32 + e] = run;
}

// ---------------------------------------------------------------------------
// Kernel 4: query kernel. One block = 32 queries. For each modality:
//   - binary search counts for first/last query (t1 sorted!)
//   - matvec against one shared exclusive-prefix state S_excl[B0]
//   - stream keys [B0*64, cnt_last) in 32-key chunks with time mask
// ---------------------------------------------------------------------------
__global__ void __launch_bounds__(256) query_kernel(
    const float* __restrict__ m1, const float* __restrict__ m2,
    const float* __restrict__ m3, const float* __restrict__ m4,
    float* __restrict__ out)
{
    __shared__ float Qs[64][33];     // [d][i]
    __shared__ float Ss[2048];       // state [d][e] = d*32+e
    __shared__ float Ks[32][68];     // key chunk [j][d]
    __shared__ float Vs[32][32];     // value chunk [j][e]
    __shared__ float sc[32][33];     // scores [j][i]
    __shared__ float t1s[32];
    __shared__ float t2s[32];
    __shared__ int   s_cnt[2];

    const int tid = threadIdx.x;
    const int i   = tid & 31;
    const int g   = tid >> 5;     // 0..7
    const int e0  = g * 4;
    const int i0  = blockIdx.x * 32;

    for (int idx = tid; idx < 2048; idx += 256) {
        int r = idx >> 6, d = idx & 63;
        Qs[d][r] = g_Q[(i0 + r) * 64 + d];
    }
    if (tid < 32) t1s[tid] = g_t2[i0 + tid];   // modality-0 times == t1

    float acc[4] = {0.f, 0.f, 0.f, 0.f};

    for (int m = 0; m < 4; m++) {
        const float* X;
        if (m == 0) X = m1; else if (m == 1) X = m2; else if (m == 2) X = m3; else X = m4;
        const int ko = c_KOFF[m];
        const int T2 = c_T2[m];

        __syncthreads();
        if (tid < 2) {
            float target = (tid == 0) ? t1s[0] : t1s[31];
            int lo = 0, hi = T2;
            while (lo < hi) {
                int mid = (lo + hi) >> 1;
                if (g_t2[ko + mid] <= target) lo = mid + 1; else hi = mid;
            }
            s_cnt[tid] = lo;
        }
        __syncthreads();
        const int cf = s_cnt[0], cl = s_cnt[1];
        const int B0 = cf >> 6;
        const int jstart = B0 << 6;
        const int jend = cl;

        const float* Sp = &g_S[(c_SOFF[m] + B0) * 2048];
        for (int idx = tid; idx < 2048; idx += 256) Ss[idx] = Sp[idx];
        __syncthreads();

        const float t1i = t1s[i];

        // matvec: acc += Q_i . S_excl[B0][:, e0..e0+3]
        #pragma unroll 8
        for (int d = 0; d < 64; d++) {
            float q = Qs[d][i];
            float4 s4 = *(const float4*)&Ss[d * 32 + e0];
            acc[0] += q * s4.x; acc[1] += q * s4.y; acc[2] += q * s4.z; acc[3] += q * s4.w;
        }

        for (int jc = jstart; jc < jend; jc += 32) {
            const int nj = min(32, jend - jc);
            __syncthreads();   // previous chunk's smem reads done
            for (int idx = tid; idx < 2048; idx += 256) {
                int j = idx >> 6, d = idx & 63;
                Ks[j][d] = (j < nj) ? g_K[(ko + jc + j) * 64 + d] : 0.0f;
            }
            for (int idx = tid; idx < 1024; idx += 256) {
                int j = idx >> 5, e = idx & 31;
                Vs[j][e] = (j < nj) ? X[(jc + j) * 64 + e] : 0.0f;
            }
            if (tid < 32) t2s[tid] = (tid < nj) ? g_t2[ko + jc + tid] : 3.0e38f;
            __syncthreads();

            // scores: thread (i,g) computes j = g*4 .. g*4+3
            const int j0 = g * 4;
            float s0 = 0.f, s1 = 0.f, s2 = 0.f, s3 = 0.f;
            #pragma unroll 8
            for (int d = 0; d < 64; d++) {
                float q = Qs[d][i];
                s0 += q * Ks[j0][d];
                s1 += q * Ks[j0 + 1][d];
                s2 += q * Ks[j0 + 2][d];
                s3 += q * Ks[j0 + 3][d];
            }
            sc[j0][i]     = (t2s[j0]     <= t1i) ? s0 : 0.0f;
            sc[j0 + 1][i] = (t2s[j0 + 1] <= t1i) ? s1 : 0.0f;
            sc[j0 + 2][i] = (t2s[j0 + 2] <= t1i) ? s2 : 0.0f;
            sc[j0 + 3][i] = (t2s[j0 + 3] <= t1i) ? s3 : 0.0f;
            __syncthreads();

            // accumulate: acc[e0..] += sum_j sc[j][i] * V[j][e0..]
            #pragma unroll 8
            for (int j = 0; j < 32; j++) {
                float s = sc[j][i];
                float4 v4 = *(const float4*)&Vs[j][e0];
                acc[0] += s * v4.x; acc[1] += s * v4.y; acc[2] += s * v4.z; acc[3] += s * v4.w;
            }
        }
    }

    float4 o4 = make_float4(acc[0], acc[1], acc[2], acc[3]);
    *(float4*)&out[(i0 + i) * 32 + e0] = o4;
}

// ---------------------------------------------------------------------------
extern "C" void kernel_launch(void* const* d_in, const int* in_sizes, int n_in,
                              void* d_out, int out_size)
{
    const float* m1   = (const float*)d_in[0];
    const float* m2   = (const float*)d_in[1];
    const float* m3   = (const float*)d_in[2];
    const float* m4   = (const float*)d_in[3];
    const float* WQ_w = (const float*)d_in[4];
    const float* WQ_b = (const float*)d_in[5];
    const float* WK_w = (const float*)d_in[6];
    const float* WK_b = (const float*)d_in[7];
    float* out = (float*)d_out;

    mlp_kernel<<<dim3(128, 5), 256>>>(m1, m2, m3, m4, WQ_w, WQ_b, WK_w, WK_b);
    blocksum_kernel<<<NOBLK, 256>>>(m1, m2, m3, m4);
    prefix_kernel<<<256, 32>>>();
    query_kernel<<<T1 / 32, 256>>>(m1, m2, m3, m4, out);
}

// round 2
// speedup vs baseline: 1.2226x; 1.2226x over previous
#include <cuda_runtime.h>

// ---------------------------------------------------------------------------
// Problem shapes
//   m1..m4 : (1,1,T,64) fp32, T = {4096, 6144, 8192, 4096}; last feature = sorted time
//   Q = mlp3(m1, WQ)  (relu, relu, linear), all 64x64
//   K_m = mlp3(m_m, WK[m]);  V_m = m_m (only first 32 cols matter)
//   out[i, :32] = sum_m sum_{j: t2m_j <= t1_i} (Q_i . Km_j) * Vm_j[:32]
// ---------------------------------------------------------------------------

#define T1        4096
#define TOTK      22528            // 4096+6144+8192+4096
#define CBLK      64               // key block size for state decomposition
#define NOBLK     352              // total key blocks (64+96+128+64)
#define NSTATE    356              // exclusive prefix states (nb+1 per modality)
#define NTILE     128              // query tiles of 32

// scratch (no allocations allowed)
__device__ float g_Q[T1 * 64];
__device__ float g_K[TOTK * 64];
__device__ float g_t2[TOTK];
__device__ float g_O[NOBLK * 2048];    // per-block sums  K^T V  (64 x 32)
__device__ float g_S[NSTATE * 2048];   // exclusive prefix states
__device__ float g_P[4][T1 * 32];      // per-modality partial outputs
__device__ int   g_cnt[NTILE][4][2];   // per (tile, modality): counts for first/last query

__constant__ int c_T2[4]   = {4096, 6144, 8192, 4096};
__constant__ int c_KOFF[4] = {0, 4096, 10240, 18432};
__constant__ int c_NB[4]   = {64, 96, 128, 64};
__constant__ int c_OOFF[5] = {0, 64, 160, 288, 352};
__constant__ int c_SOFF[4] = {0, 65, 162, 291};

// ---------------------------------------------------------------------------
// Kernel 1: fused 3-layer MLP. One block = 64-row tile of one task.
// Tasks: 0 -> Q from m1 (WQ), 1..4 -> K_m from m_m (WK[m]).
// Activations live in smem (stored k-major/transposed) across all layers.
// ---------------------------------------------------------------------------
__global__ void __launch_bounds__(256) mlp_kernel(
    const float* __restrict__ m1, const float* __restrict__ m2,
    const float* __restrict__ m3, const float* __restrict__ m4,
    const float* __restrict__ WQ_w, const float* __restrict__ WQ_b,
    const float* __restrict__ WK_w, const float* __restrict__ WK_b)
{
    __shared__ float Hs[64][68];   // [k][row]  (transposed activations)
    __shared__ float Ws[64][68];   // [k][col]
    __shared__ float bs[64];

    const int task = blockIdx.y;
    const int rowsTab[5] = {4096, 4096, 6144, 8192, 4096};
    const int rows = rowsTab[task];
    const int row0 = blockIdx.x * 64;
    if (row0 >= rows) return;

    const float* X;
    if (task <= 1)      X = m1;
    else if (task == 2) X = m2;
    else if (task == 3) X = m3;
    else                X = m4;

    const float* Wb; const float* bb; float* out;
    if (task == 0) { Wb = WQ_w; bb = WQ_b; out = g_Q; }
    else {
        int m = task - 1;
        Wb = WK_w + m * 3 * 4096;
        bb = WK_b + m * 192;
        out = g_K + c_KOFF[m] * 64;
    }

    const int tid = threadIdx.x;
    // load X tile, stored transposed
    for (int idx = tid; idx < 4096; idx += 256) {
        int r = idx >> 6, c = idx & 63;
        Hs[c][r] = X[(row0 + r) * 64 + c];
    }

    const int r0 = (tid & 15) * 4;
    const int c0 = (tid >> 4) * 4;

    for (int l = 0; l < 3; l++) {
        for (int idx = tid; idx < 4096; idx += 256)
            Ws[idx >> 6][idx & 63] = Wb[l * 4096 + idx];
        if (tid < 64) bs[tid] = bb[l * 64 + tid];
        __syncthreads();

        float acc[4][4];
        #pragma unroll
        for (int rr = 0; rr < 4; rr++)
            #pragma unroll
            for (int cc = 0; cc < 4; cc++) acc[rr][cc] = bs[c0 + cc];

        #pragma unroll 8
        for (int k = 0; k < 64; k++) {
            float4 h4 = *(const float4*)&Hs[k][r0];
            float4 w4 = *(const float4*)&Ws[k][c0];
            acc[0][0] += h4.x * w4.x; acc[0][1] += h4.x * w4.y; acc[0][2] += h4.x * w4.z; acc[0][3] += h4.x * w4.w;
            acc[1][0] += h4.y * w4.x; acc[1][1] += h4.y * w4.y; acc[1][2] += h4.y * w4.z; acc[1][3] += h4.y * w4.w;
            acc[2][0] += h4.z * w4.x; acc[2][1] += h4.z * w4.y; acc[2][2] += h4.z * w4.z; acc[2][3] += h4.z * w4.w;
            acc[3][0] += h4.w * w4.x; acc[3][1] += h4.w * w4.y; acc[3][2] += h4.w * w4.z; acc[3][3] += h4.w * w4.w;
        }
        if (l < 2) {
            #pragma unroll
            for (int rr = 0; rr < 4; rr++)
                #pragma unroll
                for (int cc = 0; cc < 4; cc++) acc[rr][cc] = fmaxf(acc[rr][cc], 0.0f);
        }
        __syncthreads();   // all reads of Hs/Ws done

        if (l < 2) {
            #pragma unroll
            for (int rr = 0; rr < 4; rr++)
                #pragma unroll
                for (int cc = 0; cc < 4; cc++)
                    Hs[c0 + cc][r0 + rr] = acc[rr][cc];
        } else {
            #pragma unroll
            for (int rr = 0; rr < 4; rr++) {
                float4 o4 = make_float4(acc[rr][0], acc[rr][1], acc[rr][2], acc[rr][3]);
                *(float4*)&out[(row0 + r0 + rr) * 64 + c0] = o4;
            }
        }
    }
}

// ---------------------------------------------------------------------------
// Kernel 2: per key-block outer-product sums O_b = K_blk^T V_blk (64 x 32),
// and extraction of contiguous time arrays.
// ---------------------------------------------------------------------------
__global__ void __launch_bounds__(256) blocksum_kernel(
    const float* __restrict__ m1, const float* __restrict__ m2,
    const float* __restrict__ m3, const float* __restrict__ m4)
{
    __shared__ float Ks[64][68];
    __shared__ float Vs[64][32];

    const int blk = blockIdx.x;
    int m = 0;
    while (blk >= c_OOFF[m + 1]) m++;
    const int local = blk - c_OOFF[m];
    const float* X;
    if (m == 0) X = m1; else if (m == 1) X = m2; else if (m == 2) X = m3; else X = m4;

    const int j0g = c_KOFF[m] + local * CBLK;  // global key row
    const int j0l = local * CBLK;              // row in X
    const int tid = threadIdx.x;

    for (int idx = tid; idx < 4096; idx += 256) {
        int j = idx >> 6, d = idx & 63;
        Ks[j][d] = g_K[(j0g + j) * 64 + d];
    }
    for (int idx = tid; idx < 2048; idx += 256) {
        int j = idx >> 5, e = idx & 31;
        Vs[j][e] = X[(j0l + j) * 64 + e];
    }
    if (tid < 64) g_t2[j0g + tid] = X[(j0l + tid) * 64 + 63];
    __syncthreads();

    const int d1 = tid & 63;
    const int gg = tid >> 6;   // 0..3 -> e0 = gg*8
    float acc[8];
    #pragma unroll
    for (int q = 0; q < 8; q++) acc[q] = 0.0f;

    #pragma unroll 8
    for (int j = 0; j < CBLK; j++) {
        float kv = Ks[j][d1];
        float4 va = *(const float4*)&Vs[j][gg * 8];
        float4 vb = *(const float4*)&Vs[j][gg * 8 + 4];
        acc[0] += kv * va.x; acc[1] += kv * va.y; acc[2] += kv * va.z; acc[3] += kv * va.w;
        acc[4] += kv * vb.x; acc[5] += kv * vb.y; acc[6] += kv * vb.z; acc[7] += kv * vb.w;
    }
    float* o = &g_O[blk * 2048 + d1 * 32 + gg * 8];
    *(float4*)o       = make_float4(acc[0], acc[1], acc[2], acc[3]);
    *(float4*)(o + 4) = make_float4(acc[4], acc[5], acc[6], acc[7]);
}

// ---------------------------------------------------------------------------
// Kernel 3: exclusive prefix over block sums. One block per (modality, d1):
// 256 blocks x 32 threads.
// ---------------------------------------------------------------------------
__global__ void __launch_bounds__(32) prefix_kernel()
{
    __shared__ float buf[128 * 32];
    const int m  = blockIdx.x >> 6;
    const int d1 = blockIdx.x & 63;
    const int nb = c_NB[m];
    const int e  = threadIdx.x;

    for (int b = 0; b < nb; b++)
        buf[b * 32 + e] = g_O[(c_OOFF[m] + b) * 2048 + d1 * 32 + e];

    float run = 0.0f;
    for (int b = 0; b < nb; b++) {
        g_S[(c_SOFF[m] + b) * 2048 + d1 * 32 + e] = run;
        run += buf[b * 32 + e];
    }
    g_S[(c_SOFF[m] + nb) * 2048 + d1 * 32 + e] = run;
}

// ---------------------------------------------------------------------------
// Kernel 3b: all 1024 tile-boundary binary searches in parallel.
// sid -> (tile, modality, first/last). t1 values are modality-0 times.
// ---------------------------------------------------------------------------
__global__ void __launch_bounds__(256) search_kernel()
{
    const int sid = blockIdx.x * 256 + threadIdx.x;
    if (sid >= NTILE * 4 * 2) return;
    const int tile = sid >> 3;
    const int m    = (sid >> 1) & 3;
    const int w    = sid & 1;
    const float target = g_t2[tile * 32 + (w ? 31 : 0)];
    const int ko = c_KOFF[m];
    int lo = 0, hi = c_T2[m];
    while (lo < hi) {
        int mid = (lo + hi) >> 1;
        if (g_t2[ko + mid] <= target) lo = mid + 1; else hi = mid;
    }
    g_cnt[tile][m][w] = lo;
}

// ---------------------------------------------------------------------------
// Kernel 4: query kernel. One block = (32-query tile, modality).
//   - matvec against one shared exclusive-prefix state S_excl[B0]
//   - stream keys [B0*64, cnt_last) in 32-key chunks with time mask
// Writes per-modality partials to g_P[m].
// ---------------------------------------------------------------------------
__global__ void __launch_bounds__(256) query_kernel(
    const float* __restrict__ m1, const float* __restrict__ m2,
    const float* __restrict__ m3, const float* __restrict__ m4)
{
    __shared__ float Qs[64][33];     // [d][i]
    __shared__ float Ss[2048];       // state [d][e] = d*32+e
    __shared__ float Ks[32][68];     // key chunk [j][d]
    __shared__ float Vs[32][32];     // value chunk [j][e]
    __shared__ float sc[32][33];     // scores [j][i]
    __shared__ float t2s[32];

    const int tid = threadIdx.x;
    const int i   = tid & 31;
    const int g   = tid >> 5;     // 0..7
    const int e0  = g * 4;
    const int tile = blockIdx.x;
    const int m    = blockIdx.y;
    const int i0   = tile * 32;

    const float* X;
    if (m == 0) X = m1; else if (m == 1) X = m2; else if (m == 2) X = m3; else X = m4;
    const int ko = c_KOFF[m];

    const int cf = g_cnt[tile][m][0];
    const int cl = g_cnt[tile][m][1];
    const int B0 = cf >> 6;
    const int jstart = B0 << 6;
    const int jend = cl;

    for (int idx = tid; idx < 2048; idx += 256) {
        int r = idx >> 6, d = idx & 63;
        Qs[d][r] = g_Q[(i0 + r) * 64 + d];
    }
    const float* Sp = &g_S[(c_SOFF[m] + B0) * 2048];
    for (int idx = tid; idx < 2048; idx += 256) Ss[idx] = Sp[idx];
    const float t1i = g_t2[i0 + i];    // modality-0 times == t1
    __syncthreads();

    float acc[4] = {0.f, 0.f, 0.f, 0.f};

    // matvec: acc += Q_i . S_excl[B0][:, e0..e0+3]
    #pragma unroll 8
    for (int d = 0; d < 64; d++) {
        float q = Qs[d][i];
        float4 s4 = *(const float4*)&Ss[d * 32 + e0];
        acc[0] += q * s4.x; acc[1] += q * s4.y; acc[2] += q * s4.z; acc[3] += q * s4.w;
    }

    for (int jc = jstart; jc < jend; jc += 32) {
        const int nj = min(32, jend - jc);
        __syncthreads();   // previous chunk's smem reads done
        for (int idx = tid; idx < 2048; idx += 256) {
            int j = idx >> 6, d = idx & 63;
            Ks[j][d] = (j < nj) ? g_K[(ko + jc + j) * 64 + d] : 0.0f;
        }
        for (int idx = tid; idx < 1024; idx += 256) {
            int j = idx >> 5, e = idx & 31;
            Vs[j][e] = (j < nj) ? X[(jc + j) * 64 + e] : 0.0f;
        }
        if (tid < 32) t2s[tid] = (tid < nj) ? g_t2[ko + jc + tid] : 3.0e38f;
        __syncthreads();

        // scores: thread (i,g) computes j = g*4 .. g*4+3
        const int j0 = g * 4;
        float s0 = 0.f, s1 = 0.f, s2 = 0.f, s3 = 0.f;
        #pragma unroll 8
        for (int d = 0; d < 64; d++) {
            float q = Qs[d][i];
            s0 += q * Ks[j0][d];
            s1 += q * Ks[j0 + 1][d];
            s2 += q * Ks[j0 + 2][d];
            s3 += q * Ks[j0 + 3][d];
        }
        sc[j0][i]     = (t2s[j0]     <= t1i) ? s0 : 0.0f;
        sc[j0 + 1][i] = (t2s[j0 + 1] <= t1i) ? s1 : 0.0f;
        sc[j0 + 2][i] = (t2s[j0 + 2] <= t1i) ? s2 : 0.0f;
        sc[j0 + 3][i] = (t2s[j0 + 3] <= t1i) ? s3 : 0.0f;
        __syncthreads();

        // accumulate: acc[e0..] += sum_j sc[j][i] * V[j][e0..]
        #pragma unroll 8
        for (int j = 0; j < 32; j++) {
            float s = sc[j][i];
            float4 v4 = *(const float4*)&Vs[j][e0];
            acc[0] += s * v4.x; acc[1] += s * v4.y; acc[2] += s * v4.z; acc[3] += s * v4.w;
        }
    }

    float4 o4 = make_float4(acc[0], acc[1], acc[2], acc[3]);
    *(float4*)&g_P[m][(i0 + i) * 32 + e0] = o4;
}

// ---------------------------------------------------------------------------
// Kernel 5: sum the 4 per-modality partials into the output.
// ---------------------------------------------------------------------------
__global__ void __launch_bounds__(256) reduce_kernel(float* __restrict__ out)
{
    const int idx = (blockIdx.x * 256 + threadIdx.x);   // float4 index
    if (idx >= T1 * 32 / 4) return;
    float4 a = ((const float4*)g_P[0])[idx];
    float4 b = ((const float4*)g_P[1])[idx];
    float4 c = ((const float4*)g_P[2])[idx];
    float4 d = ((const float4*)g_P[3])[idx];
    float4 o;
    o.x = (a.x + b.x) + (c.x + d.x);
    o.y = (a.y + b.y) + (c.y + d.y);
    o.z = (a.z + b.z) + (c.z + d.z);
    o.w = (a.w + b.w) + (c.w + d.w);
    ((float4*)out)[idx] = o;
}

// ---------------------------------------------------------------------------
extern "C" void kernel_launch(void* const* d_in, const int* in_sizes, int n_in,
                              void* d_out, int out_size)
{
    const float* m1   = (const float*)d_in[0];
    const float* m2   = (const float*)d_in[1];
    const float* m3   = (const float*)d_in[2];
    const float* m4   = (const float*)d_in[3];
    const float* WQ_w = (const float*)d_in[4];
    const float* WQ_b = (const float*)d_in[5];
    const float* WK_w = (const float*)d_in[6];
    const float* WK_b = (const float*)d_in[7];
    float* out = (float*)d_out;

    mlp_kernel<<<dim3(128, 5), 256>>>(m1, m2, m3, m4, WQ_w, WQ_b, WK_w, WK_b);
    blocksum_kernel<<<NOBLK, 256>>>(m1, m2, m3, m4);
    search_kernel<<<4, 256>>>();
    prefix_kernel<<<256, 32>>>();
    query_kernel<<<dim3(NTILE, 4), 256>>>(m1, m2, m3, m4);
    reduce_kernel<<<(T1 * 32 / 4 + 255) / 256, 256>>>(out);
}

// round 3
// speedup vs baseline: 1.3510x; 1.1051x over previous
#include <cuda_runtime.h>

// ---------------------------------------------------------------------------
// out[i, :32] = sum_m sum_{j: t2m_j <= t1_i} (Q_i . Km_j) * Vm_j[:32]
//   Q = mlp3(m1, WQ); K_m = mlp3(m_m, WK[m]); V_m = m_m[:, :32]
// ---------------------------------------------------------------------------

#define T1        4096
#define TOTK      22528            // 4096+6144+8192+4096
#define CBLK      64               // key block size for state decomposition
#define NOBLK     352              // total key blocks (64+96+128+64)
#define NSTATE    356              // exclusive prefix states (nb+1 per modality)
#define NTILE     128              // query tiles of 32
#define NCHUNK    22               // key-block chunks of 16 (4+6+8+4)

// scratch (no allocations allowed)
__device__ float g_Q[T1 * 64];
__device__ float g_K[TOTK * 64];
__device__ float g_t2[TOTK];
__device__ float g_O[NOBLK * 2048];    // per-block sums  K^T V  (64 x 32)
__device__ float g_S[NSTATE * 2048];   // exclusive prefix states
__device__ float g_CT[NCHUNK * 2048];  // chunk totals
__device__ float g_CS[NCHUNK * 2048];  // chunk exclusive prefixes
__device__ float g_P[4][T1 * 32];      // per-modality partial outputs
__device__ int   g_cnt[NTILE][4][2];   // per (tile, modality): counts for first/last query

__constant__ int c_T2[4]    = {4096, 6144, 8192, 4096};
__constant__ int c_KOFF[4]  = {0, 4096, 10240, 18432};
__constant__ int c_NB[4]    = {64, 96, 128, 64};
__constant__ int c_OOFF[5]  = {0, 64, 160, 288, 352};
__constant__ int c_SOFF[4]  = {0, 65, 162, 291};
__constant__ int c_CHOFF[5] = {0, 4, 10, 18, 22};

// ---------------------------------------------------------------------------
// Kernel 1: fused 3-layer MLP. One block = 64-row tile of one task.
// ---------------------------------------------------------------------------
__global__ void __launch_bounds__(256) mlp_kernel(
    const float* __restrict__ m1, const float* __restrict__ m2,
    const float* __restrict__ m3, const float* __restrict__ m4,
    const float* __restrict__ WQ_w, const float* __restrict__ WQ_b,
    const float* __restrict__ WK_w, const float* __restrict__ WK_b)
{
    __shared__ float Hs[64][68];   // [k][row]  (transposed activations)
    __shared__ float Ws[64][68];   // [k][col]
    __shared__ float bs[64];

    const int task = blockIdx.y;
    const int rowsTab[5] = {4096, 4096, 6144, 8192, 4096};
    const int rows = rowsTab[task];
    const int row0 = blockIdx.x * 64;
    if (row0 >= rows) return;

    const float* X;
    if (task <= 1)      X = m1;
    else if (task == 2) X = m2;
    else if (task == 3) X = m3;
    else                X = m4;

    const float* Wb; const float* bb; float* out;
    if (task == 0) { Wb = WQ_w; bb = WQ_b; out = g_Q; }
    else {
        int m = task - 1;
        Wb = WK_w + m * 3 * 4096;
        bb = WK_b + m * 192;
        out = g_K + c_KOFF[m] * 64;
    }

    const int tid = threadIdx.x;
    for (int idx = tid; idx < 4096; idx += 256) {
        int r = idx >> 6, c = idx & 63;
        Hs[c][r] = X[(row0 + r) * 64 + c];
    }

    const int r0 = (tid & 15) * 4;
    const int c0 = (tid >> 4) * 4;

    for (int l = 0; l < 3; l++) {
        for (int idx = tid; idx < 4096; idx += 256)
            Ws[idx >> 6][idx & 63] = Wb[l * 4096 + idx];
        if (tid < 64) bs[tid] = bb[l * 64 + tid];
        __syncthreads();

        float acc[4][4];
        #pragma unroll
        for (int rr = 0; rr < 4; rr++)
            #pragma unroll
            for (int cc = 0; cc < 4; cc++) acc[rr][cc] = bs[c0 + cc];

        #pragma unroll 8
        for (int k = 0; k < 64; k++) {
            float4 h4 = *(const float4*)&Hs[k][r0];
            float4 w4 = *(const float4*)&Ws[k][c0];
            acc[0][0] += h4.x * w4.x; acc[0][1] += h4.x * w4.y; acc[0][2] += h4.x * w4.z; acc[0][3] += h4.x * w4.w;
            acc[1][0] += h4.y * w4.x; acc[1][1] += h4.y * w4.y; acc[1][2] += h4.y * w4.z; acc[1][3] += h4.y * w4.w;
            acc[2][0] += h4.z * w4.x; acc[2][1] += h4.z * w4.y; acc[2][2] += h4.z * w4.z; acc[2][3] += h4.z * w4.w;
            acc[3][0] += h4.w * w4.x; acc[3][1] += h4.w * w4.y; acc[3][2] += h4.w * w4.z; acc[3][3] += h4.w * w4.w;
        }
        if (l < 2) {
            #pragma unroll
            for (int rr = 0; rr < 4; rr++)
                #pragma unroll
                for (int cc = 0; cc < 4; cc++) acc[rr][cc] = fmaxf(acc[rr][cc], 0.0f);
        }
        __syncthreads();

        if (l < 2) {
            #pragma unroll
            for (int rr = 0; rr < 4; rr++)
                #pragma unroll
                for (int cc = 0; cc < 4; cc++)
                    Hs[c0 + cc][r0 + rr] = acc[rr][cc];
        } else {
            #pragma unroll
            for (int rr = 0; rr < 4; rr++) {
                float4 o4 = make_float4(acc[rr][0], acc[rr][1], acc[rr][2], acc[rr][3]);
                *(float4*)&out[(row0 + r0 + rr) * 64 + c0] = o4;
            }
        }
    }
}

// ---------------------------------------------------------------------------
// Kernel 2: per key-block outer-product sums O_b = K_blk^T V_blk (64 x 32),
// and extraction of contiguous time arrays.
// ---------------------------------------------------------------------------
__global__ void __launch_bounds__(256) blocksum_kernel(
    const float* __restrict__ m1, const float* __restrict__ m2,
    const float* __restrict__ m3, const float* __restrict__ m4)
{
    __shared__ float Ks[64][68];
    __shared__ float Vs[64][32];

    const int blk = blockIdx.x;
    int m = 0;
    while (blk >= c_OOFF[m + 1]) m++;
    const int local = blk - c_OOFF[m];
    const float* X;
    if (m == 0) X = m1; else if (m == 1) X = m2; else if (m == 2) X = m3; else X = m4;

    const int j0g = c_KOFF[m] + local * CBLK;
    const int j0l = local * CBLK;
    const int tid = threadIdx.x;

    for (int idx = tid; idx < 4096; idx += 256) {
        int j = idx >> 6, d = idx & 63;
        Ks[j][d] = g_K[(j0g + j) * 64 + d];
    }
    for (int idx = tid; idx < 2048; idx += 256) {
        int j = idx >> 5, e = idx & 31;
        Vs[j][e] = X[(j0l + j) * 64 + e];
    }
    if (tid < 64) g_t2[j0g + tid] = X[(j0l + tid) * 64 + 63];
    __syncthreads();

    const int d1 = tid & 63;
    const int gg = tid >> 6;
    float acc[8];
    #pragma unroll
    for (int q = 0; q < 8; q++) acc[q] = 0.0f;

    #pragma unroll 8
    for (int j = 0; j < CBLK; j++) {
        float kv = Ks[j][d1];
        float4 va = *(const float4*)&Vs[j][gg * 8];
        float4 vb = *(const float4*)&Vs[j][gg * 8 + 4];
        acc[0] += kv * va.x; acc[1] += kv * va.y; acc[2] += kv * va.z; acc[3] += kv * va.w;
        acc[4] += kv * vb.x; acc[5] += kv * vb.y; acc[6] += kv * vb.z; acc[7] += kv * vb.w;
    }
    float* o = &g_O[blk * 2048 + d1 * 32 + gg * 8];
    *(float4*)o       = make_float4(acc[0], acc[1], acc[2], acc[3]);
    *(float4*)(o + 4) = make_float4(acc[4], acc[5], acc[6], acc[7]);
}

// ---------------------------------------------------------------------------
// Prefix scan, 3-level chunked (chunk = 16 key blocks).
// ---------------------------------------------------------------------------
// Pass 1: chunk totals. thread <-> (chunk, elem). 16 independent loads each.
__global__ void __launch_bounds__(256) chunksum_kernel()
{
    const int gidx = blockIdx.x * 256 + threadIdx.x;   // 22*2048
    const int ch   = gidx >> 11;
    const int el   = gidx & 2047;
    int m = 0;
    while (ch >= c_CHOFF[m + 1]) m++;
    const int b0 = c_OOFF[m] + (ch - c_CHOFF[m]) * 16;

    float v[16];
    #pragma unroll
    for (int b = 0; b < 16; b++) v[b] = g_O[(b0 + b) * 2048 + el];
    float s = 0.0f;
    #pragma unroll
    for (int b = 0; b < 16; b++) s += v[b];
    g_CT[ch * 2048 + el] = s;
}

// Pass 2: exclusive scan of chunk totals within each modality.
// thread <-> (m, elem): 4*2048 = 8192 threads.
__global__ void __launch_bounds__(256) chunkscan_kernel()
{
    const int gidx = blockIdx.x * 256 + threadIdx.x;
    const int m    = gidx >> 11;
    const int el   = gidx & 2047;
    const int c0   = c_CHOFF[m];
    const int nch  = c_CHOFF[m + 1] - c0;

    float v[8];
    #pragma unroll
    for (int c = 0; c < 8; c++)
        v[c] = (c < nch) ? g_CT[(c0 + c) * 2048 + el] : 0.0f;
    float run = 0.0f;
    #pragma unroll
    for (int c = 0; c < 8; c++) {
        if (c < nch) g_CS[(c0 + c) * 2048 + el] = run;
        run += v[c];
    }
}

// Pass 3: final exclusive prefixes. thread <-> (chunk, elem).
// Preload 16 values, register scan, write 16 (+1 for last chunk) outputs.
__global__ void __launch_bounds__(256) finalprefix_kernel()
{
    const int gidx = blockIdx.x * 256 + threadIdx.x;
    const int ch   = gidx >> 11;
    const int el   = gidx & 2047;
    int m = 0;
    while (ch >= c_CHOFF[m + 1]) m++;
    const int lc = ch - c_CHOFF[m];
    const int b0o = c_OOFF[m] + lc * 16;   // in g_O
    const int b0s = c_SOFF[m] + lc * 16;   // in g_S

    float v[16];
    #pragma unroll
    for (int b = 0; b < 16; b++) v[b] = g_O[(b0o + b) * 2048 + el];

    float run = g_CS[ch * 2048 + el];
    #pragma unroll
    for (int b = 0; b < 16; b++) {
        g_S[(b0s + b) * 2048 + el] = run;
        run += v[b];
    }
    if (lc == c_CHOFF[m + 1] - c_CHOFF[m] - 1)   // last chunk: inclusive total
        g_S[(c_SOFF[m] + c_NB[m]) * 2048 + el] = run;
}

// ---------------------------------------------------------------------------
// Kernel 3b: all 1024 tile-boundary binary searches in parallel.
// ---------------------------------------------------------------------------
__global__ void __launch_bounds__(256) search_kernel()
{
    const int sid = blockIdx.x * 256 + threadIdx.x;
    if (sid >= NTILE * 4 * 2) return;
    const int tile = sid >> 3;
    const int m    = (sid >> 1) & 3;
    const int w    = sid & 1;
    const float target = g_t2[tile * 32 + (w ? 31 : 0)];
    const int ko = c_KOFF[m];
    int lo = 0, hi = c_T2[m];
    while (lo < hi) {
        int mid = (lo + hi) >> 1;
        if (g_t2[ko + mid] <= target) lo = mid + 1; else hi = mid;
    }
    g_cnt[tile][m][w] = lo;
}

// ---------------------------------------------------------------------------
// Kernel 4: query kernel. One block = (32-query tile, modality).
// ---------------------------------------------------------------------------
__global__ void __launch_bounds__(256) query_kernel(
    const float* __restrict__ m1, const float* __restrict__ m2,
    const float* __restrict__ m3, const float* __restrict__ m4)
{
    __shared__ float Qs[64][33];
    __shared__ float Ss[2048];
    __shared__ float Ks[32][68];
    __shared__ float Vs[32][32];
    __shared__ float sc[32][33];
    __shared__ float t2s[32];

    const int tid = threadIdx.x;
    const int i   = tid & 31;
    const int g   = tid >> 5;
    const int e0  = g * 4;
    const int tile = blockIdx.x;
    const int m    = blockIdx.y;
    const int i0   = tile * 32;

    const float* X;
    if (m == 0) X = m1; else if (m == 1) X = m2; else if (m == 2) X = m3; else X = m4;
    const int ko = c_KOFF[m];

    const int cf = g_cnt[tile][m][0];
    const int cl = g_cnt[tile][m][1];
    const int B0 = cf >> 6;
    const int jstart = B0 << 6;
    const int jend = cl;

    for (int idx = tid; idx < 2048; idx += 256) {
        int r = idx >> 6, d = idx & 63;
        Qs[d][r] = g_Q[(i0 + r) * 64 + d];
    }
    const float* Sp = &g_S[(c_SOFF[m] + B0) * 2048];
    for (int idx = tid; idx < 2048; idx += 256) Ss[idx] = Sp[idx];
    const float t1i = g_t2[i0 + i];
    __syncthreads();

    float acc[4] = {0.f, 0.f, 0.f, 0.f};

    #pragma unroll 8
    for (int d = 0; d < 64; d++) {
        float q = Qs[d][i];
        float4 s4 = *(const float4*)&Ss[d * 32 + e0];
        acc[0] += q * s4.x; acc[1] += q * s4.y; acc[2] += q * s4.z; acc[3] += q * s4.w;
    }

    for (int jc = jstart; jc < jend; jc += 32) {
        const int nj = min(32, jend - jc);
        __syncthreads();
        for (int idx = tid; idx < 2048; idx += 256) {
            int j = idx >> 6, d = idx & 63;
            Ks[j][d] = (j < nj) ? g_K[(ko + jc + j) * 64 + d] : 0.0f;
        }
        for (int idx = tid; idx < 1024; idx += 256) {
            int j = idx >> 5, e = idx & 31;
            Vs[j][e] = (j < nj) ? X[(jc + j) * 64 + e] : 0.0f;
        }
        if (tid < 32) t2s[tid] = (tid < nj) ? g_t2[ko + jc + tid] : 3.0e38f;
        __syncthreads();

        const int j0 = g * 4;
        float s0 = 0.f, s1 = 0.f, s2 = 0.f, s3 = 0.f;
        #pragma unroll 8
        for (int d = 0; d < 64; d++) {
            float q = Qs[d][i];
            s0 += q * Ks[j0][d];
            s1 += q * Ks[j0 + 1][d];
            s2 += q * Ks[j0 + 2][d];
            s3 += q * Ks[j0 + 3][d];
        }
        sc[j0][i]     = (t2s[j0]     <= t1i) ? s0 : 0.0f;
        sc[j0 + 1][i] = (t2s[j0 + 1] <= t1i) ? s1 : 0.0f;
        sc[j0 + 2][i] = (t2s[j0 + 2] <= t1i) ? s2 : 0.0f;
        sc[j0 + 3][i] = (t2s[j0 + 3] <= t1i) ? s3 : 0.0f;
        __syncthreads();

        #pragma unroll 8
        for (int j = 0; j < 32; j++) {
            float s = sc[j][i];
            float4 v4 = *(const float4*)&Vs[j][e0];
            acc[0] += s * v4.x; acc[1] += s * v4.y; acc[2] += s * v4.z; acc[3] += s * v4.w;
        }
    }

    float4 o4 = make_float4(acc[0], acc[1], acc[2], acc[3]);
    *(float4*)&g_P[m][(i0 + i) * 32 + e0] = o4;
}

// ---------------------------------------------------------------------------
// Kernel 5: sum the 4 per-modality partials into the output.
// ---------------------------------------------------------------------------
__global__ void __launch_bounds__(256) reduce_kernel(float* __restrict__ out)
{
    const int idx = (blockIdx.x * 256 + threadIdx.x);
    if (idx >= T1 * 32 / 4) return;
    float4 a = ((const float4*)g_P[0])[idx];
    float4 b = ((const float4*)g_P[1])[idx];
    float4 c = ((const float4*)g_P[2])[idx];
    float4 d = ((const float4*)g_P[3])[idx];
    float4 o;
    o.x = (a.x + b.x) + (c.x + d.x);
    o.y = (a.y + b.y) + (c.y + d.y);
    o.z = (a.z + b.z) + (c.z + d.z);
    o.w = (a.w + b.w) + (c.w + d.w);
    ((float4*)out)[idx] = o;
}

// ---------------------------------------------------------------------------
extern "C" void kernel_launch(void* const* d_in, const int* in_sizes, int n_in,
                              void* d_out, int out_size)
{
    const float* m1   = (const float*)d_in[0];
    const float* m2   = (const float*)d_in[1];
    const float* m3   = (const float*)d_in[2];
    const float* m4   = (const float*)d_in[3];
    const float* WQ_w = (const float*)d_in[4];
    const float* WQ_b = (const float*)d_in[5];
    const float* WK_w = (const float*)d_in[6];
    const float* WK_b = (const float*)d_in[7];
    float* out = (float*)d_out;

    mlp_kernel<<<dim3(128, 5), 256>>>(m1, m2, m3, m4, WQ_w, WQ_b, WK_w, WK_b);
    blocksum_kernel<<<NOBLK, 256>>>(m1, m2, m3, m4);
    search_kernel<<<4, 256>>>();
    chunksum_kernel<<<NCHUNK * 2048 / 256, 256>>>();
    chunkscan_kernel<<<4 * 2048 / 256, 256>>>();
    finalprefix_kernel<<<NCHUNK * 2048 / 256, 256>>>();
    query_kernel<<<dim3(NTILE, 4), 256>>>(m1, m2, m3, m4);
    reduce_kernel<<<(T1 * 32 / 4 + 255) / 256, 256>>>(out);
}

// round 4
// speedup vs baseline: 1.3953x; 1.0327x over previous
#include <cuda_runtime.h>

// ---------------------------------------------------------------------------
// out[i, :32] = sum_m sum_{j: t2m_j <= t1_i} (Q_i . Km_j) * Vm_j[:32]
//   Q = mlp3(m1, WQ); K_m = mlp3(m_m, WK[m]); V_m = m_m[:, :32]
// ---------------------------------------------------------------------------

#define T1        4096
#define TOTK      22528            // 4096+6144+8192+4096
#define CBLK      64               // key block size
#define NOBLK     352              // total key blocks (64+96+128+64)
#define NSTATE    356              // exclusive prefix states (nb+1 per modality)
#define NTILE     128              // query tiles of 32

typedef unsigned long long u64;

__device__ __forceinline__ u64 pk2(float lo, float hi) {
    u64 r; asm("mov.b64 %0,{%1,%2};" : "=l"(r) : "f"(lo), "f"(hi)); return r;
}
__device__ __forceinline__ void upk2(u64 v, float& lo, float& hi) {
    asm("mov.b64 {%0,%1},%2;" : "=f"(lo), "=f"(hi) : "l"(v));
}
__device__ __forceinline__ void ffma2(u64& d, u64 a, u64 b) {
    asm("fma.rn.f32x2 %0,%1,%2,%0;" : "+l"(d) : "l"(a), "l"(b));
}

// scratch (no allocations allowed)
__device__ float g_Q[T1 * 64];
__device__ float g_K[TOTK * 64];
__device__ float g_t2[TOTK];
__device__ float g_O[NOBLK * 2048];    // per-block sums  K^T V  (64 x 32)
__device__ float g_S[NSTATE * 2048];   // exclusive prefix states
__device__ float g_P[4][T1 * 32];      // per-modality partial outputs
__device__ int   g_cnt[NTILE][4][2];

__constant__ int c_T2[4]    = {4096, 6144, 8192, 4096};
__constant__ int c_KOFF[4]  = {0, 4096, 10240, 18432};
__constant__ int c_NB[4]    = {64, 96, 128, 64};
__constant__ int c_OOFF[5]  = {0, 64, 160, 288, 352};
__constant__ int c_SOFF[4]  = {0, 65, 162, 291};

// ---------------------------------------------------------------------------
// Kernel 1: fused 3-layer MLP. 128 threads, 64-row tile, 4x8 thread tiles,
// f32x2 packed FMA (pairs along the col axis come free from ulonglong2 LDS).
// ---------------------------------------------------------------------------
__global__ void __launch_bounds__(128) mlp_kernel(
    const float* __restrict__ m1, const float* __restrict__ m2,
    const float* __restrict__ m3, const float* __restrict__ m4,
    const float* __restrict__ WQ_w, const float* __restrict__ WQ_b,
    const float* __restrict__ WK_w, const float* __restrict__ WK_b)
{
    __shared__ float Hs[64][68];   // [k][row]  (transposed activations)
    __shared__ float Ws[64][68];   // [k][col]
    __shared__ float bs[64];

    const int task = blockIdx.y;
    const int rowsTab[5] = {4096, 4096, 6144, 8192, 4096};
    const int rows = rowsTab[task];
    const int row0 = blockIdx.x * 64;
    if (row0 >= rows) return;

    const float* X;
    if (task <= 1)      X = m1;
    else if (task == 2) X = m2;
    else if (task == 3) X = m3;
    else                X = m4;

    const float* Wb; const float* bb; float* out;
    if (task == 0) { Wb = WQ_w; bb = WQ_b; out = g_Q; }
    else {
        int m = task - 1;
        Wb = WK_w + m * 3 * 4096;
        bb = WK_b + m * 192;
        out = g_K + c_KOFF[m] * 64;
    }

    const int tid = threadIdx.x;
    for (int idx = tid; idx < 4096; idx += 128) {
        int r = idx >> 6, c = idx & 63;
        Hs[c][r] = X[(row0 + r) * 64 + c];
    }

    const int r0 = (tid & 15) * 4;     // 16 row groups
    const int c0 = (tid >> 4) * 8;     // 8 col groups

    for (int l = 0; l < 3; l++) {
        for (int idx = tid; idx < 4096; idx += 128)
            Ws[idx >> 6][idx & 63] = Wb[l * 4096 + idx];
        if (tid < 64) bs[tid] = bb[l * 64 + tid];
        __syncthreads();

        u64 acc[4][4];   // [row][col-pair]
        #pragma unroll
        for (int rr = 0; rr < 4; rr++)
            #pragma unroll
            for (int cp = 0; cp < 4; cp++)
                acc[rr][cp] = pk2(bs[c0 + 2 * cp], bs[c0 + 2 * cp + 1]);

        #pragma unroll 8
        for (int k = 0; k < 64; k++) {
            float4 h = *(const float4*)&Hs[k][r0];
            ulonglong2 wa = *(const ulonglong2*)&Ws[k][c0];
            ulonglong2 wb2 = *(const ulonglong2*)&Ws[k][c0 + 4];
            u64 hd0 = pk2(h.x, h.x), hd1 = pk2(h.y, h.y);
            u64 hd2 = pk2(h.z, h.z), hd3 = pk2(h.w, h.w);
            ffma2(acc[0][0], hd0, wa.x); ffma2(acc[0][1], hd0, wa.y);
            ffma2(acc[0][2], hd0, wb2.x); ffma2(acc[0][3], hd0, wb2.y);
            ffma2(acc[1][0], hd1, wa.x); ffma2(acc[1][1], hd1, wa.y);
            ffma2(acc[1][2], hd1, wb2.x); ffma2(acc[1][3], hd1, wb2.y);
            ffma2(acc[2][0], hd2, wa.x); ffma2(acc[2][1], hd2, wa.y);
            ffma2(acc[2][2], hd2, wb2.x); ffma2(acc[2][3], hd2, wb2.y);
            ffma2(acc[3][0], hd3, wa.x); ffma2(acc[3][1], hd3, wa.y);
            ffma2(acc[3][2], hd3, wb2.x); ffma2(acc[3][3], hd3, wb2.y);
        }

        float a[4][8];
        #pragma unroll
        for (int rr = 0; rr < 4; rr++)
            #pragma unroll
            for (int cp = 0; cp < 4; cp++)
                upk2(acc[rr][cp], a[rr][2 * cp], a[rr][2 * cp + 1]);

        if (l < 2) {
            #pragma unroll
            for (int rr = 0; rr < 4; rr++)
                #pragma unroll
                for (int cc = 0; cc < 8; cc++) a[rr][cc] = fmaxf(a[rr][cc], 0.0f);
        }
        __syncthreads();

        if (l < 2) {
            #pragma unroll
            for (int cc = 0; cc < 8; cc++) {
                float4 v = make_float4(a[0][cc], a[1][cc], a[2][cc], a[3][cc]);
                *(float4*)&Hs[c0 + cc][r0] = v;
            }
        } else {
            #pragma unroll
            for (int rr = 0; rr < 4; rr++) {
                *(float4*)&out[(row0 + r0 + rr) * 64 + c0] =
                    make_float4(a[rr][0], a[rr][1], a[rr][2], a[rr][3]);
                *(float4*)&out[(row0 + r0 + rr) * 64 + c0 + 4] =
                    make_float4(a[rr][4], a[rr][5], a[rr][6], a[rr][7]);
            }
        }
    }
}

// ---------------------------------------------------------------------------
// Kernel 2: per key-block outer-product sums O_b = K_blk^T V_blk (64 x 32),
// and extraction of contiguous time arrays. f32x2 packed.
// ---------------------------------------------------------------------------
__global__ void __launch_bounds__(256) blocksum_kernel(
    const float* __restrict__ m1, const float* __restrict__ m2,
    const float* __restrict__ m3, const float* __restrict__ m4)
{
    __shared__ float Ks[64][68];
    __shared__ float Vs[64][32];

    const int blk = blockIdx.x;
    int m = 0;
    while (blk >= c_OOFF[m + 1]) m++;
    const int local = blk - c_OOFF[m];
    const float* X;
    if (m == 0) X = m1; else if (m == 1) X = m2; else if (m == 2) X = m3; else X = m4;

    const int j0g = c_KOFF[m] + local * CBLK;
    const int j0l = local * CBLK;
    const int tid = threadIdx.x;

    for (int idx = tid; idx < 4096; idx += 256) {
        int j = idx >> 6, d = idx & 63;
        Ks[j][d] = g_K[(j0g + j) * 64 + d];
    }
    for (int idx = tid; idx < 2048; idx += 256) {
        int j = idx >> 5, e = idx & 31;
        Vs[j][e] = X[(j0l + j) * 64 + e];
    }
    if (tid < 64) g_t2[j0g + tid] = X[(j0l + tid) * 64 + 63];
    __syncthreads();

    const int d1 = tid & 63;
    const int gg = tid >> 6;   // 0..3 -> e0 = gg*8
    u64 acc[4] = {0ULL, 0ULL, 0ULL, 0ULL};

    #pragma unroll 8
    for (int j = 0; j < CBLK; j++) {
        float kv = Ks[j][d1];
        u64 kd = pk2(kv, kv);
        ulonglong2 va = *(const ulonglong2*)&Vs[j][gg * 8];
        ulonglong2 vb = *(const ulonglong2*)&Vs[j][gg * 8 + 4];
        ffma2(acc[0], kd, va.x); ffma2(acc[1], kd, va.y);
        ffma2(acc[2], kd, vb.x); ffma2(acc[3], kd, vb.y);
    }
    float a[8];
    upk2(acc[0], a[0], a[1]); upk2(acc[1], a[2], a[3]);
    upk2(acc[2], a[4], a[5]); upk2(acc[3], a[6], a[7]);
    float* o = &g_O[blk * 2048 + d1 * 32 + gg * 8];
    *(float4*)o       = make_float4(a[0], a[1], a[2], a[3]);
    *(float4*)(o + 4) = make_float4(a[4], a[5], a[6], a[7]);
}

// ---------------------------------------------------------------------------
// Kernel 3: fused exclusive scan. One thread per (modality, elem): 8192
// threads. 16-wide unrolled batches (independent loads), register scan.
// ---------------------------------------------------------------------------
__global__ void __launch_bounds__(128) scan_kernel()
{
    const int gidx = blockIdx.x * 128 + threadIdx.x;   // 4*2048
    const int m  = gidx >> 11;
    const int el = gidx & 2047;
    const int nb = c_NB[m];
    const float* src = &g_O[c_OOFF[m] * 2048 + el];
    float* dst = &g_S[c_SOFF[m] * 2048 + el];

    float run = 0.0f;
    for (int b0 = 0; b0 < nb; b0 += 16) {
        float v[16];
        #pragma unroll
        for (int b = 0; b < 16; b++) v[b] = src[(b0 + b) * 2048];
        #pragma unroll
        for (int b = 0; b < 16; b++) { dst[(b0 + b) * 2048] = run; run += v[b]; }
    }
    dst[nb * 2048] = run;
}

// ---------------------------------------------------------------------------
// Kernel 3b: all 1024 tile-boundary binary searches in parallel.
// ---------------------------------------------------------------------------
__global__ void __launch_bounds__(256) search_kernel()
{
    const int sid = blockIdx.x * 256 + threadIdx.x;
    if (sid >= NTILE * 4 * 2) return;
    const int tile = sid >> 3;
    const int m    = (sid >> 1) & 3;
    const int w    = sid & 1;
    const float target = g_t2[tile * 32 + (w ? 31 : 0)];
    const int ko = c_KOFF[m];
    int lo = 0, hi = c_T2[m];
    while (lo < hi) {
        int mid = (lo + hi) >> 1;
        if (g_t2[ko + mid] <= target) lo = mid + 1; else hi = mid;
    }
    g_cnt[tile][m][w] = lo;
}

// ---------------------------------------------------------------------------
// Kernel 4: query kernel. One block = (32-query tile, modality). f32x2.
// Ks stored transposed [d][j] so scores use broadcast packed loads.
// ---------------------------------------------------------------------------
__global__ void __launch_bounds__(256) query_kernel(
    const float* __restrict__ m1, const float* __restrict__ m2,
    const float* __restrict__ m3, const float* __restrict__ m4)
{
    __shared__ float Qs[64][33];     // [d][i]
    __shared__ float Ss[2048];       // state [d][e]
    __shared__ float Ks[64][36];     // key chunk [d][j]  (transposed, 16B-aligned rows)
    __shared__ float Vs[32][32];     // value chunk [j][e]
    __shared__ float sc[32][33];     // scores [j][i]
    __shared__ float t2s[32];

    const int tid = threadIdx.x;
    const int i   = tid & 31;
    const int g   = tid >> 5;
    const int e0  = g * 4;
    const int tile = blockIdx.x;
    const int m    = blockIdx.y;
    const int i0   = tile * 32;

    const float* X;
    if (m == 0) X = m1; else if (m == 1) X = m2; else if (m == 2) X = m3; else X = m4;
    const int ko = c_KOFF[m];

    const int cf = g_cnt[tile][m][0];
    const int cl = g_cnt[tile][m][1];
    const int B0 = cf >> 6;
    const int jstart = B0 << 6;
    const int jend = cl;

    for (int idx = tid; idx < 2048; idx += 256) {
        int r = idx >> 6, d = idx & 63;
        Qs[d][r] = g_Q[(i0 + r) * 64 + d];
    }
    const float* Sp = &g_S[(c_SOFF[m] + B0) * 2048];
    for (int idx = tid; idx < 2048; idx += 256) Ss[idx] = Sp[idx];
    const float t1i = g_t2[i0 + i];
    __syncthreads();

    u64 a01 = 0ULL, a23 = 0ULL;   // output accumulators (e0..e0+3)

    // matvec: acc += Q_i . S_excl[B0][:, e0..e0+3]
    #pragma unroll 8
    for (int d = 0; d < 64; d++) {
        float q = Qs[d][i];
        u64 qd = pk2(q, q);
        ulonglong2 s2 = *(const ulonglong2*)&Ss[d * 32 + e0];
        ffma2(a01, qd, s2.x); ffma2(a23, qd, s2.y);
    }

    for (int jc = jstart; jc < jend; jc += 32) {
        const int nj = min(32, jend - jc);
        __syncthreads();
        for (int idx = tid; idx < 2048; idx += 256) {
            int j = idx >> 6, d = idx & 63;
            Ks[d][j] = (j < nj) ? g_K[(ko + jc + j) * 64 + d] : 0.0f;
        }
        for (int idx = tid; idx < 1024; idx += 256) {
            int j = idx >> 5, e = idx & 31;
            Vs[j][e] = (j < nj) ? X[(jc + j) * 64 + e] : 0.0f;
        }
        if (tid < 32) t2s[tid] = (tid < nj) ? g_t2[ko + jc + tid] : 3.0e38f;
        __syncthreads();

        // scores: thread (i,g) computes j = g*4 .. g*4+3
        const int j0 = g * 4;
        u64 s01 = 0ULL, s23 = 0ULL;
        #pragma unroll 8
        for (int d = 0; d < 64; d++) {
            float q = Qs[d][i];
            u64 qd = pk2(q, q);
            ulonglong2 k2 = *(const ulonglong2*)&Ks[d][j0];
            ffma2(s01, qd, k2.x); ffma2(s23, qd, k2.y);
        }
        float s0, s1, s2v, s3;
        upk2(s01, s0, s1); upk2(s23, s2v, s3);
        sc[j0][i]     = (t2s[j0]     <= t1i) ? s0  : 0.0f;
        sc[j0 + 1][i] = (t2s[j0 + 1] <= t1i) ? s1  : 0.0f;
        sc[j0 + 2][i] = (t2s[j0 + 2] <= t1i) ? s2v : 0.0f;
        sc[j0 + 3][i] = (t2s[j0 + 3] <= t1i) ? s3  : 0.0f;
        __syncthreads();

        // accumulate: acc[e0..] += sum_j sc[j][i] * V[j][e0..]
        #pragma unroll 8
        for (int j = 0; j < 32; j++) {
            float s = sc[j][i];
            u64 sd = pk2(s, s);
            ulonglong2 v2 = *(const ulonglong2*)&Vs[j][e0];
            ffma2(a01, sd, v2.x); ffma2(a23, sd, v2.y);
        }
    }

    float o0, o1, o2, o3;
    upk2(a01, o0, o1); upk2(a23, o2, o3);
    *(float4*)&g_P[m][(i0 + i) * 32 + e0] = make_float4(o0, o1, o2, o3);
}

// ---------------------------------------------------------------------------
// Kernel 5: sum the 4 per-modality partials into the output.
// ---------------------------------------------------------------------------
__global__ void __launch_bounds__(256) reduce_kernel(float* __restrict__ out)
{
    const int idx = (blockIdx.x * 256 + threadIdx.x);
    if (idx >= T1 * 32 / 4) return;
    float4 a = ((const float4*)g_P[0])[idx];
    float4 b = ((const float4*)g_P[1])[idx];
    float4 c = ((const float4*)g_P[2])[idx];
    float4 d = ((const float4*)g_P[3])[idx];
    float4 o;
    o.x = (a.x + b.x) + (c.x + d.x);
    o.y = (a.y + b.y) + (c.y + d.y);
    o.z = (a.z + b.z) + (c.z + d.z);
    o.w = (a.w + b.w) + (c.w + d.w);
    ((float4*)out)[idx] = o;
}

// ---------------------------------------------------------------------------
extern "C" void kernel_launch(void* const* d_in, const int* in_sizes, int n_in,
                              void* d_out, int out_size)
{
    const float* m1   = (const float*)d_in[0];
    const float* m2   = (const float*)d_in[1];
    const float* m3   = (const float*)d_in[2];
    const float* m4   = (const float*)d_in[3];
    const float* WQ_w = (const float*)d_in[4];
    const float* WQ_b = (const float*)d_in[5];
    const float* WK_w = (const float*)d_in[6];
    const float* WK_b = (const float*)d_in[7];
    float* out = (float*)d_out;

    mlp_kernel<<<dim3(128, 5), 128>>>(m1, m2, m3, m4, WQ_w, WQ_b, WK_w, WK_b);
    blocksum_kernel<<<NOBLK, 256>>>(m1, m2, m3, m4);
    search_kernel<<<4, 256>>>();
    scan_kernel<<<64, 128>>>();
    query_kernel<<<dim3(NTILE, 4), 256>>>(m1, m2, m3, m4);
    reduce_kernel<<<(T1 * 32 / 4 + 255) / 256, 256>>>(out);
}